// round 7
// baseline (speedup 1.0000x reference)
#include <cuda_runtime.h>
#include <math_constants.h>

#define NT 1024      // threads per CTA (one CTA per row)
#define NC 16384     // candidate capacity

// order-preserving float<->uint (ascending)
__device__ __forceinline__ unsigned f2o(float f) {
    unsigned u = __float_as_uint(f);
    return u ^ ((u & 0x80000000u) ? 0xFFFFFFFFu : 0x80000000u);
}
__device__ __forceinline__ float o2f(unsigned u) {
    unsigned v = u ^ ((u & 0x80000000u) ? 0x80000000u : 0xFFFFFFFFu);
    return __uint_as_float(v);
}

__device__ __forceinline__ float blk_max(float v, float* w, int tid) {
    #pragma unroll
    for (int o = 16; o; o >>= 1) v = fmaxf(v, __shfl_xor_sync(0xFFFFFFFFu, v, o));
    if ((tid & 31) == 0) w[tid >> 5] = v;
    __syncthreads();
    if (tid < 32) {
        float x = w[tid];
        #pragma unroll
        for (int o = 16; o; o >>= 1) x = fmaxf(x, __shfl_xor_sync(0xFFFFFFFFu, x, o));
        if (tid == 0) w[0] = x;
    }
    __syncthreads();
    float r = w[0];
    __syncthreads();
    return r;
}
__device__ __forceinline__ float blk_sumf(float v, float* w, int tid) {
    #pragma unroll
    for (int o = 16; o; o >>= 1) v += __shfl_xor_sync(0xFFFFFFFFu, v, o);
    if ((tid & 31) == 0) w[tid >> 5] = v;
    __syncthreads();
    if (tid < 32) {
        float x = w[tid];
        #pragma unroll
        for (int o = 16; o; o >>= 1) x += __shfl_xor_sync(0xFFFFFFFFu, x, o);
        if (tid == 0) w[0] = x;
    }
    __syncthreads();
    float r = w[0];
    __syncthreads();
    return r;
}

__global__ __launch_bounds__(NT, 1)
void sampler_kernel(const float* __restrict__ logits,
                    const float* __restrict__ temps,
                    const int*   __restrict__ topks,
                    const float* __restrict__ topps,
                    const float* __restrict__ minps,
                    const float* __restrict__ noise,
                    float* __restrict__ out, int V)
{
    extern __shared__ unsigned char smem_raw[];
    float* s_val = (float*)smem_raw;             // NC candidate values x = l/T
    int*   s_idx = (int*)(s_val + NC);           // NC candidate indices
    int*   s_h   = (int*)(s_idx + NC);           // 256 bins (int or float via cast)
    int*   s_s   = s_h + 256;                    // 256 suffix sums

    __shared__ float wf[32];
    __shared__ int   wi[32];
    __shared__ int   sh_cnt, sh_sel;

    const int tid = threadIdx.x;
    const int row = blockIdx.x;
    const float* lg = logits + (size_t)row * V;
    const float* nz = noise  + (size_t)row * V;
    const float T = temps[row];
    int k = topks[row]; if (k < 1) k = 1; if (k > V) k = V;
    const float p  = topps[row];
    const float mp = minps[row];
    const int lane = tid & 31;
    const unsigned lml = (1u << lane) - 1u;

    const float4* lg4 = (const float4*)lg;
    const int V4 = V >> 2;

    // ================= pass A: row max of raw logits (no div) =================
    float a0 = -CUDART_INF_F, a1 = -CUDART_INF_F, a2 = -CUDART_INF_F, a3 = -CUDART_INF_F;
    int i = tid;
    for (; i + 3 * NT < V4; i += 4 * NT) {
        float4 x0 = lg4[i];          float4 x1 = lg4[i + NT];
        float4 x2 = lg4[i + 2 * NT]; float4 x3 = lg4[i + 3 * NT];
        a0 = fmaxf(a0, fmaxf(fmaxf(x0.x, x0.y), fmaxf(x0.z, x0.w)));
        a1 = fmaxf(a1, fmaxf(fmaxf(x1.x, x1.y), fmaxf(x1.z, x1.w)));
        a2 = fmaxf(a2, fmaxf(fmaxf(x2.x, x2.y), fmaxf(x2.z, x2.w)));
        a3 = fmaxf(a3, fmaxf(fmaxf(x3.x, x3.y), fmaxf(x3.z, x3.w)));
    }
    for (; i < V4; i += NT) {
        float4 x0 = lg4[i];
        a0 = fmaxf(a0, fmaxf(fmaxf(x0.x, x0.y), fmaxf(x0.z, x0.w)));
    }
    for (int j = (V4 << 2) + tid; j < V; j += NT) a0 = fmaxf(a0, lg[j]);
    const float Ml = blk_max(fmaxf(fmaxf(a0, a1), fmaxf(a2, a3)), wf, tid);
    const float M  = __fdiv_rn(Ml, T);   // == per-element divided value of the max element

    // ================= pass B: gather candidates l >= Ml - win ================
    int n = 0;
    float win = 2.8f;
    for (int att = 0; att < 10; ++att) {
        float bound = Ml - win;
        if (tid == 0) sh_cnt = 0;
        __syncthreads();
        const int iters = (V4 + NT - 1) / NT;
        for (int it = 0; it < iters; ++it) {
            int i2 = tid + it * NT;
            bool in = i2 < V4;
            float4 v = in ? lg4[i2] : make_float4(-1e30f, -1e30f, -1e30f, -1e30f);
            float comp[4] = {v.x, v.y, v.z, v.w};
            #pragma unroll
            for (int c = 0; c < 4; ++c) {
                bool hit = in && (comp[c] >= bound);
                unsigned mask = __ballot_sync(0xFFFFFFFFu, hit);
                if (mask) {
                    int leader = __ffs(mask) - 1;
                    int base = 0;
                    if (lane == leader) base = atomicAdd(&sh_cnt, __popc(mask));
                    base = __shfl_sync(0xFFFFFFFFu, base, leader);
                    if (hit) {
                        int pos = base + __popc(mask & lml);
                        if (pos < NC) { s_val[pos] = __fdiv_rn(comp[c], T); s_idx[pos] = (i2 << 2) + c; }
                    }
                }
            }
        }
        for (int j = (V4 << 2) + tid; j < V; j += NT) {
            float l = lg[j];
            if (l >= bound) {
                int pos = atomicAdd(&sh_cnt, 1);
                if (pos < NC) { s_val[pos] = __fdiv_rn(l, T); s_idx[pos] = j; }
            }
        }
        __syncthreads();
        n = sh_cnt;
        __syncthreads();
        if (n >= k && n <= NC) break;
        win = (n < k) ? win * 1.5f : win * 0.6f;
    }
    if (n > NC) n = NC;
    if (k > n) k = n;
    const int npad = (n + 31) & ~31;

    // ============ count radix-select: thrO = k-th largest (ordered uint) =========
    unsigned thrO = 0;
    {
        unsigned pref = 0;
        int krem = k;
        for (int byte = 3; byte >= 0; --byte) {
            for (int b = tid; b < 256; b += NT) s_h[b] = 0;
            __syncthreads();
            const unsigned hm = (byte == 3) ? 0u : (0xFFFFFFFFu << (8 * (byte + 1)));
            for (int j = tid; j < npad; j += NT) {
                bool valid = j < n;
                unsigned u = valid ? f2o(s_val[j]) : 0u;
                bool act = valid && ((u & hm) == (pref & hm));
                int bin = act ? (int)((u >> (8 * byte)) & 255u) : -1;
                unsigned mm = __match_any_sync(0xFFFFFFFFu, bin);
                if (act) {
                    int leader = __ffs(mm) - 1;
                    if (lane == leader) atomicAdd(&s_h[bin], __popc(mm));
                }
            }
            __syncthreads();
            // warp-0 suffix scan of 256 bins (8 bins/lane)
            if (tid < 32) {
                int base = tid * 8;
                int v[8]; int sum = 0;
                #pragma unroll
                for (int q = 0; q < 8; ++q) { v[q] = s_h[base + q]; sum += v[q]; }
                int incl = sum;
                #pragma unroll
                for (int o = 1; o < 32; o <<= 1) {
                    int t = __shfl_down_sync(0xFFFFFFFFu, incl, o);
                    if (tid + o < 32) incl += t;
                }
                int run = incl - sum;   // tail over lanes > tid
                #pragma unroll
                for (int q = 7; q >= 0; --q) { run += v[q]; s_s[base + q] = run; }
            }
            __syncthreads();
            if (tid < 256) {
                int s = s_s[tid];
                int nx = (tid == 255) ? 0 : s_s[tid + 1];
                if (s >= krem && nx < krem) sh_sel = tid;
            }
            __syncthreads();
            int sel = sh_sel;
            krem -= (sel == 255) ? 0 : s_s[sel + 1];
            pref |= (unsigned)sel << (8 * byte);
            __syncthreads();
        }
        thrO = pref;
    }

    // ================= Z1 = sum exp(x - M) over top-k survivors ==================
    float z = 0.f;
    for (int j = tid; j < n; j += NT) {
        float x = s_val[j];
        if (f2o(x) >= thrO) z += expf(x - M);
    }
    const float Z1 = blk_sumf(z, wf, tid);

    // ===== mass radix-select: v2O = value where top-mass first reaches p*Z1 ======
    // kept-after-top-p = { x : f2o(x) >= v2O }  (suffix-cum > 1-p  <=>  strictly-
    // greater mass < p*Z1; boundary element included)
    unsigned v2O = thrO;
    {
        float* s_hf = (float*)s_h;
        float* s_sf = (float*)s_s;
        float tr = p * Z1;
        unsigned pref = 0;
        for (int byte = 3; byte >= 0; --byte) {
            for (int b = tid; b < 256; b += NT) s_hf[b] = 0.f;
            __syncthreads();
            const unsigned hm = (byte == 3) ? 0u : (0xFFFFFFFFu << (8 * (byte + 1)));
            for (int j = tid; j < npad; j += NT) {
                bool valid = j < n;
                float x = valid ? s_val[j] : 0.f;
                unsigned u = f2o(x);
                bool act = valid && (u >= thrO) && ((u & hm) == (pref & hm));
                float pm = act ? expf(x - M) : 0.f;
                int bin = act ? (int)((u >> (8 * byte)) & 255u) : -1;
                unsigned mm = __match_any_sync(0xFFFFFFFFu, bin);
                if (mm == 0xFFFFFFFFu) {          // whole warp same bin: one atomic
                    float s = pm;
                    #pragma unroll
                    for (int o = 16; o; o >>= 1) s += __shfl_xor_sync(0xFFFFFFFFu, s, o);
                    if (lane == 0 && bin >= 0) atomicAdd(&s_hf[bin], s);
                } else if (act) {
                    atomicAdd(&s_hf[bin], pm);
                }
            }
            __syncthreads();
            if (tid < 32) {                        // warp-0 float suffix scan
                int base = tid * 8;
                float v[8]; float sum = 0.f;
                #pragma unroll
                for (int q = 0; q < 8; ++q) { v[q] = s_hf[base + q]; sum += v[q]; }
                float incl = sum;
                #pragma unroll
                for (int o = 1; o < 32; o <<= 1) {
                    float t = __shfl_down_sync(0xFFFFFFFFu, incl, o);
                    if (tid + o < 32) incl += t;
                }
                float run = incl - sum;
                #pragma unroll
                for (int q = 7; q >= 0; --q) { run += v[q]; s_sf[base + q] = run; }
            }
            __syncthreads();
            // clamp tr into (0, S_total] so exactly one bin is selected
            float tt = fminf(tr, s_sf[0]);
            tt = fmaxf(tt, 1e-35f);
            if (tid < 256) {
                float s = s_sf[tid];
                float nx = (tid == 255) ? 0.f : s_sf[tid + 1];
                if (s >= tt && nx < tt) sh_sel = tid;
            }
            __syncthreads();
            int sel = sh_sel;
            tr = tt - ((sel == 255) ? 0.f : s_sf[sel + 1]);
            pref |= (unsigned)sel << (8 * byte);
            __syncthreads();
        }
        v2O = pref;
    }

    // ========== final: argmax of exp(x-M)/max(noise,1e-10) over kept set =========
    const bool usemp = (mp > 0.f);
    float bv = -1.f; int bi = 0x7FFFFFFF;
    for (int j = tid; j < n; j += NT) {
        float x = s_val[j];
        if (f2o(x) >= v2O) {                       // top-k & top-p survivors
            float e = expf(x - M);
            if (!usemp || e >= mp) {               // min-p (argmax e=1 always kept)
                int ix = s_idx[j];
                float sc = __fdiv_rn(e, fmaxf(nz[ix], 1e-10f));
                if (sc > bv || (sc == bv && ix < bi)) { bv = sc; bi = ix; }
            }
        }
    }
    #pragma unroll
    for (int o = 16; o; o >>= 1) {
        float ov = __shfl_xor_sync(0xFFFFFFFFu, bv, o);
        int   oi = __shfl_xor_sync(0xFFFFFFFFu, bi, o);
        if (ov > bv || (ov == bv && oi < bi)) { bv = ov; bi = oi; }
    }
    if (lane == 0) { wf[tid >> 5] = bv; wi[tid >> 5] = bi; }
    __syncthreads();
    if (tid < 32) {
        float xv = wf[tid];
        int   xi = wi[tid];
        #pragma unroll
        for (int o = 16; o; o >>= 1) {
            float ov = __shfl_xor_sync(0xFFFFFFFFu, xv, o);
            int   oi = __shfl_xor_sync(0xFFFFFFFFu, xi, o);
            if (ov > xv || (ov == xv && oi < xi)) { xv = ov; xi = oi; }
        }
        if (tid == 0) out[row] = (float)xi;
    }
}

extern "C" void kernel_launch(void* const* d_in, const int* in_sizes, int n_in,
                              void* d_out, int out_size)
{
    const float* logits = (const float*)d_in[0];
    const float* temps  = (const float*)d_in[1];
    const int*   topks  = (const int*)d_in[2];
    const float* topps  = (const float*)d_in[3];
    const float* minps  = (const float*)d_in[4];
    const float* noise  = (const float*)d_in[5];
    const int B = out_size;              // output: [B] sampled indices (float32)
    const int V = in_sizes[0] / B;       // logits: [B, V]

    const size_t smem = (size_t)NC * 8 + 512 * sizeof(int);
    cudaFuncSetAttribute(sampler_kernel,
                         cudaFuncAttributeMaxDynamicSharedMemorySize, (int)smem);
    sampler_kernel<<<B, NT, smem>>>(logits, temps, topks, topps, minps, noise,
                                    (float*)d_out, V);
}

// round 8
// speedup vs baseline: 1.9212x; 1.9212x over previous
#include <cuda_runtime.h>
#include <math_constants.h>

#define NT 1024      // threads per CTA (one CTA per row)
#define NC 8192      // candidate capacity
#define HB 2048      // histogram bins over [-16,16), width 1/64 (raw logits)

// order-preserving float<->uint (ascending)
__device__ __forceinline__ unsigned f2o(float f) {
    unsigned u = __float_as_uint(f);
    return u ^ ((u & 0x80000000u) ? 0xFFFFFFFFu : 0x80000000u);
}
__device__ __forceinline__ int binraw(float l) {
    float t = (l + 16.0f) * 64.0f;
    int b = (int)t;
    if (t < 0.f) b = 0;
    if (b > HB - 1) b = HB - 1;
    return b;
}

__device__ __forceinline__ float blk_max(float v, float* w, int tid) {
    #pragma unroll
    for (int o = 16; o; o >>= 1) v = fmaxf(v, __shfl_xor_sync(0xFFFFFFFFu, v, o));
    if ((tid & 31) == 0) w[tid >> 5] = v;
    __syncthreads();
    if (tid < 32) {
        float x = w[tid];
        #pragma unroll
        for (int o = 16; o; o >>= 1) x = fmaxf(x, __shfl_xor_sync(0xFFFFFFFFu, x, o));
        if (tid == 0) w[0] = x;
    }
    __syncthreads();
    float r = w[0];
    __syncthreads();
    return r;
}
__device__ __forceinline__ float blk_sumf(float v, float* w, int tid) {
    #pragma unroll
    for (int o = 16; o; o >>= 1) v += __shfl_xor_sync(0xFFFFFFFFu, v, o);
    if ((tid & 31) == 0) w[tid >> 5] = v;
    __syncthreads();
    if (tid < 32) {
        float x = w[tid];
        #pragma unroll
        for (int o = 16; o; o >>= 1) x += __shfl_xor_sync(0xFFFFFFFFu, x, o);
        if (tid == 0) w[0] = x;
    }
    __syncthreads();
    float r = w[0];
    __syncthreads();
    return r;
}

__global__ __launch_bounds__(NT, 1)
void sampler_kernel(const float* __restrict__ logits,
                    const float* __restrict__ temps,
                    const int*   __restrict__ topks,
                    const float* __restrict__ topps,
                    const float* __restrict__ minps,
                    const float* __restrict__ noise,
                    float* __restrict__ out, int V)
{
    extern __shared__ unsigned char smem_raw[];
    float* s_val  = (float*)smem_raw;            // NC candidate values x = l/T
    int*   s_idx  = (int*)(s_val + NC);          // NC candidate indices
    int*   s_hist = (int*)(s_idx + NC);          // HB hist; [0..255] reused by radix
    int*   s_sa   = s_hist + HB;                 // HB scan ping; [0..255] radix suffix
    int*   s_sb   = s_sa + HB;                   // HB scan pong

    __shared__ float wf[32];
    __shared__ int   sh_wi[32];
    __shared__ int   sh_cnt, sh_sel, sh_bcut;

    const int tid = threadIdx.x;
    const int row = blockIdx.x;
    const float* lg = logits + (size_t)row * V;
    const float* nz = noise  + (size_t)row * V;
    const float T = temps[row];
    int k = topks[row]; if (k < 1) k = 1; if (k > V) k = V;
    const float p  = topps[row];
    const float mp = minps[row];
    const int lane = tid & 31;
    const unsigned lml = (1u << lane) - 1u;

    const float4* lg4 = (const float4*)lg;
    const int V4 = V >> 2;

    // ========== pass 0: fused row max + histogram of RAW logits (4x batched) =====
    for (int b = tid; b < HB; b += NT) s_hist[b] = 0;
    __syncthreads();

    float lmax = -CUDART_INF_F;
    int i = tid;
    for (; i + 3 * NT < V4; i += 4 * NT) {
        float4 v0 = lg4[i];          float4 v1 = lg4[i + NT];
        float4 v2 = lg4[i + 2 * NT]; float4 v3 = lg4[i + 3 * NT];
        lmax = fmaxf(lmax, fmaxf(fmaxf(v0.x, v0.y), fmaxf(v0.z, v0.w)));
        lmax = fmaxf(lmax, fmaxf(fmaxf(v1.x, v1.y), fmaxf(v1.z, v1.w)));
        lmax = fmaxf(lmax, fmaxf(fmaxf(v2.x, v2.y), fmaxf(v2.z, v2.w)));
        lmax = fmaxf(lmax, fmaxf(fmaxf(v3.x, v3.y), fmaxf(v3.z, v3.w)));
        atomicAdd(&s_hist[binraw(v0.x)], 1); atomicAdd(&s_hist[binraw(v0.y)], 1);
        atomicAdd(&s_hist[binraw(v0.z)], 1); atomicAdd(&s_hist[binraw(v0.w)], 1);
        atomicAdd(&s_hist[binraw(v1.x)], 1); atomicAdd(&s_hist[binraw(v1.y)], 1);
        atomicAdd(&s_hist[binraw(v1.z)], 1); atomicAdd(&s_hist[binraw(v1.w)], 1);
        atomicAdd(&s_hist[binraw(v2.x)], 1); atomicAdd(&s_hist[binraw(v2.y)], 1);
        atomicAdd(&s_hist[binraw(v2.z)], 1); atomicAdd(&s_hist[binraw(v2.w)], 1);
        atomicAdd(&s_hist[binraw(v3.x)], 1); atomicAdd(&s_hist[binraw(v3.y)], 1);
        atomicAdd(&s_hist[binraw(v3.z)], 1); atomicAdd(&s_hist[binraw(v3.w)], 1);
    }
    for (; i < V4; i += NT) {
        float4 v0 = lg4[i];
        lmax = fmaxf(lmax, fmaxf(fmaxf(v0.x, v0.y), fmaxf(v0.z, v0.w)));
        atomicAdd(&s_hist[binraw(v0.x)], 1); atomicAdd(&s_hist[binraw(v0.y)], 1);
        atomicAdd(&s_hist[binraw(v0.z)], 1); atomicAdd(&s_hist[binraw(v0.w)], 1);
    }
    for (int j = (V4 << 2) + tid; j < V; j += NT) {
        float l = lg[j];
        lmax = fmaxf(lmax, l);
        atomicAdd(&s_hist[binraw(l)], 1);
    }
    const float Ml = blk_max(lmax, wf, tid);
    const float M  = __fdiv_rn(Ml, T);   // divided value of the max element

    // ====== suffix-sum histogram (exact counts), pick cutoff bin: cum >= k =======
    {
        int* ia = s_sa; int* ib = s_sb;
        for (int b = tid; b < HB; b += NT) ia[b] = s_hist[b];
        __syncthreads();
        for (int d = 1; d < HB; d <<= 1) {
            for (int b = tid; b < HB; b += NT)
                ib[b] = ia[b] + ((b + d < HB) ? ia[b + d] : 0);
            __syncthreads();
            int* t = ia; ia = ib; ib = t;
        }
        for (int b = tid; b < HB; b += NT) {
            int s = ia[b];
            int nx = (b == HB - 1) ? 0 : ia[b + 1];
            if (s >= k && nx < k) sh_bcut = b;
        }
        __syncthreads();
    }
    const int bcut = sh_bcut;

    // ========== gather pass: compact raw-bin >= bcut, store x = l/T ==============
    if (tid == 0) sh_cnt = 0;
    __syncthreads();
    {
        const int iters = (V4 + NT - 1) / NT;
        for (int it = 0; it < iters; ++it) {
            int i2 = tid + it * NT;
            bool in = i2 < V4;
            float4 v = in ? lg4[i2] : make_float4(-1e30f, -1e30f, -1e30f, -1e30f);
            float comp[4] = {v.x, v.y, v.z, v.w};
            #pragma unroll
            for (int c = 0; c < 4; ++c) {
                bool hit = in && (binraw(comp[c]) >= bcut);
                unsigned mask = __ballot_sync(0xFFFFFFFFu, hit);
                if (mask) {
                    int leader = __ffs(mask) - 1;
                    int base = 0;
                    if (lane == leader) base = atomicAdd(&sh_cnt, __popc(mask));
                    base = __shfl_sync(0xFFFFFFFFu, base, leader);
                    if (hit) {
                        int pos = base + __popc(mask & lml);
                        if (pos < NC) { s_val[pos] = __fdiv_rn(comp[c], T); s_idx[pos] = (i2 << 2) + c; }
                    }
                }
            }
        }
        for (int j = (V4 << 2) + tid; j < V; j += NT) {
            float l = lg[j];
            if (binraw(l) >= bcut) {
                int pos = atomicAdd(&sh_cnt, 1);
                if (pos < NC) { s_val[pos] = __fdiv_rn(l, T); s_idx[pos] = j; }
            }
        }
    }
    __syncthreads();
    int n = sh_cnt; if (n > NC) n = NC;
    if (k > n) k = n;
    __syncthreads();

    // ========= count radix-select: thrO = k-th largest x (ordered uint) ==========
    unsigned thrO = 0;
    {
        unsigned pref = 0;
        int krem = k;
        for (int byte = 3; byte >= 0; --byte) {
            for (int b = tid; b < 256; b += NT) s_hist[b] = 0;
            __syncthreads();
            const unsigned hm = (byte == 3) ? 0u : (0xFFFFFFFFu << (8 * (byte + 1)));
            for (int j = tid; j < n; j += NT) {
                unsigned u = f2o(s_val[j]);
                if ((u & hm) == (pref & hm))
                    atomicAdd(&s_hist[(u >> (8 * byte)) & 255u], 1);
            }
            __syncthreads();
            if (tid < 32) {                 // warp-0 suffix scan of 256 bins
                int base = tid * 8;
                int v[8]; int sum = 0;
                #pragma unroll
                for (int q = 0; q < 8; ++q) { v[q] = s_hist[base + q]; sum += v[q]; }
                int incl = sum;
                #pragma unroll
                for (int o = 1; o < 32; o <<= 1) {
                    int t = __shfl_down_sync(0xFFFFFFFFu, incl, o);
                    if (tid + o < 32) incl += t;
                }
                int run = incl - sum;
                #pragma unroll
                for (int q = 7; q >= 0; --q) { run += v[q]; s_sa[base + q] = run; }
            }
            __syncthreads();
            if (tid < 256) {
                int s = s_sa[tid];
                int nx = (tid == 255) ? 0 : s_sa[tid + 1];
                if (s >= krem && nx < krem) sh_sel = tid;
            }
            __syncthreads();
            int sel = sh_sel;
            krem -= (sel == 255) ? 0 : s_sa[sel + 1];
            pref |= (unsigned)sel << (8 * byte);
            __syncthreads();
        }
        thrO = pref;
    }

    // ================= Z1 = sum exp(x - M) over top-k survivors ==================
    float z = 0.f;
    for (int j = tid; j < n; j += NT) {
        float x = s_val[j];
        if (f2o(x) >= thrO) z += expf(x - M);
    }
    const float Z1 = blk_sumf(z, wf, tid);

    // ===== mass radix-select: v2O = value where top-mass first reaches p*Z1 ======
    // kept-after-top-p = { x : f2o(x) >= v2O }
    unsigned v2O = thrO;
    {
        float* s_hf = (float*)s_hist;
        float* s_sf = (float*)s_sa;
        float tr = p * Z1;
        unsigned pref = 0;
        for (int byte = 3; byte >= 0; --byte) {
            for (int b = tid; b < 256; b += NT) s_hf[b] = 0.f;
            __syncthreads();
            const unsigned hm = (byte == 3) ? 0u : (0xFFFFFFFFu << (8 * (byte + 1)));
            for (int j = tid; j < n; j += NT) {
                float x = s_val[j];
                unsigned u = f2o(x);
                if (u >= thrO && (u & hm) == (pref & hm))
                    atomicAdd(&s_hf[(u >> (8 * byte)) & 255u], expf(x - M));
            }
            __syncthreads();
            if (tid < 32) {                 // warp-0 float suffix scan
                int base = tid * 8;
                float v[8]; float sum = 0.f;
                #pragma unroll
                for (int q = 0; q < 8; ++q) { v[q] = s_hf[base + q]; sum += v[q]; }
                float incl = sum;
                #pragma unroll
                for (int o = 1; o < 32; o <<= 1) {
                    float t = __shfl_down_sync(0xFFFFFFFFu, incl, o);
                    if (tid + o < 32) incl += t;
                }
                float run = incl - sum;
                #pragma unroll
                for (int q = 7; q >= 0; --q) { run += v[q]; s_sf[base + q] = run; }
            }
            __syncthreads();
            float tt = fminf(tr, s_sf[0]);  // clamp so exactly one bin selected
            tt = fmaxf(tt, 1e-35f);
            if (tid < 256) {
                float s = s_sf[tid];
                float nx = (tid == 255) ? 0.f : s_sf[tid + 1];
                if (s >= tt && nx < tt) sh_sel = tid;
            }
            __syncthreads();
            int sel = sh_sel;
            tr = tt - ((sel == 255) ? 0.f : s_sf[sel + 1]);
            pref |= (unsigned)sel << (8 * byte);
            __syncthreads();
        }
        v2O = pref;
    }

    // ========== final: argmax of exp(x-M)/max(noise,1e-10) over kept set =========
    const bool usemp = (mp > 0.f);
    float bv = -1.f; int bi = 0x7FFFFFFF;
    for (int j = tid; j < n; j += NT) {
        float x = s_val[j];
        if (f2o(x) >= v2O) {                  // top-k & top-p survivors
            float e = expf(x - M);
            if (!usemp || e >= mp) {          // min-p (argmax e=1 always kept)
                int ix = s_idx[j];
                float sc = __fdiv_rn(e, fmaxf(nz[ix], 1e-10f));
                if (sc > bv || (sc == bv && ix < bi)) { bv = sc; bi = ix; }
            }
        }
    }
    #pragma unroll
    for (int o = 16; o; o >>= 1) {
        float ov = __shfl_xor_sync(0xFFFFFFFFu, bv, o);
        int   oi = __shfl_xor_sync(0xFFFFFFFFu, bi, o);
        if (ov > bv || (ov == bv && oi < bi)) { bv = ov; bi = oi; }
    }
    if (lane == 0) { wf[tid >> 5] = bv; sh_wi[tid >> 5] = bi; }
    __syncthreads();
    if (tid < 32) {
        float xv = wf[tid];
        int   xi = sh_wi[tid];
        #pragma unroll
        for (int o = 16; o; o >>= 1) {
            float ov = __shfl_xor_sync(0xFFFFFFFFu, xv, o);
            int   oi = __shfl_xor_sync(0xFFFFFFFFu, xi, o);
            if (ov > xv || (ov == xv && oi < xi)) { xv = ov; xi = oi; }
        }
        if (tid == 0) out[row] = (float)xi;
    }
}

extern "C" void kernel_launch(void* const* d_in, const int* in_sizes, int n_in,
                              void* d_out, int out_size)
{
    const float* logits = (const float*)d_in[0];
    const float* temps  = (const float*)d_in[1];
    const int*   topks  = (const int*)d_in[2];
    const float* topps  = (const float*)d_in[3];
    const float* minps  = (const float*)d_in[4];
    const float* noise  = (const float*)d_in[5];
    const int B = out_size;              // output: [B] sampled indices (float32)
    const int V = in_sizes[0] / B;       // logits: [B, V]

    const size_t smem = (size_t)NC * 8 + (size_t)HB * 3 * sizeof(int);
    cudaFuncSetAttribute(sampler_kernel,
                         cudaFuncAttributeMaxDynamicSharedMemorySize, (int)smem);
    sampler_kernel<<<B, NT, smem>>>(logits, temps, topks, topps, minps, noise,
                                    (float*)d_out, V);
}